// round 15
// baseline (speedup 1.0000x reference)
#include <cuda_runtime.h>
#include <cuda_bf16.h>
#include <cstdint>

// DCTExtractor: gray = 0.299R + 0.587G + 0.114B, per-8x8-block 2D DCT
// (D @ blk @ D^T) * mask, folded back to (B,1,H,W).
//
// R13 structure (one thread per 8x8 block, register DCT, __ldcs streaming
// LDG.128 reads, smem-staged cp.async.bulk output) widened to 2 block-rows
// per CTA: TPB=128, one 32KB bulk store per CTA (2048 stores instead of
// 4096x16KB). Same 128-reg budget, same 16 warps/SM, same concurrency —
// isolates write-burst granularity.

#define TPB 128

__device__ __forceinline__ uint32_t smem_u32(const void* p) {
    uint32_t a;
    asm("{ .reg .u64 t; cvta.to.shared.u64 t, %1; cvt.u32.u64 %0, t; }"
        : "=r"(a) : "l"(p));
    return a;
}

__global__ __launch_bounds__(TPB, 4)
void dct_extract_kernel(const float* __restrict__ x,
                        const float* __restrict__ dctm,
                        const float* __restrict__ mask,
                        float* __restrict__ out,
                        int ntiles)
{
    __shared__ float Ds[64];
    __shared__ float Ms[64];
    __shared__ __align__(16) float stage[8192];   // 32KB: 16 output image rows

    const int t = threadIdx.x;
    if (t < 64)       Ds[t]      = dctm[t];
    else if (t < 128) Ms[t - 64] = mask[t - 64];
    __syncthreads();

    const int W  = 512;
    const int HW = 512 * 512;

    // tile = 2 consecutive block-rows of one image (32 per image)
    const int T = blockIdx.x;
    const int b   = T >> 5;
    const int byp = T & 31;
    const int rsel = t >> 6;            // 0 or 1: which block-row
    const int bx   = t & 63;            // block column
    const int by   = byp * 2 + rsel;

    const float* p0 = x + (size_t)b * 3 * HW + (size_t)(by * 8) * W + bx * 8;

    // ---- load 8x8 grayscale block into registers (LDG.128, evict-first) ----
    float g[8][8];
#pragma unroll
    for (int j = 0; j < 8; ++j) {
        const float* row = p0 + j * W;
        const float4 r0 = __ldcs((const float4*)(row));
        const float4 r1 = __ldcs((const float4*)(row + 4));
        const float4 g0 = __ldcs((const float4*)(row + HW));
        const float4 g1 = __ldcs((const float4*)(row + HW + 4));
        const float4 b0 = __ldcs((const float4*)(row + 2 * HW));
        const float4 b1 = __ldcs((const float4*)(row + 2 * HW + 4));
        g[j][0] = fmaf(0.114f, b0.x, fmaf(0.587f, g0.x, 0.299f * r0.x));
        g[j][1] = fmaf(0.114f, b0.y, fmaf(0.587f, g0.y, 0.299f * r0.y));
        g[j][2] = fmaf(0.114f, b0.z, fmaf(0.587f, g0.z, 0.299f * r0.z));
        g[j][3] = fmaf(0.114f, b0.w, fmaf(0.587f, g0.w, 0.299f * r0.w));
        g[j][4] = fmaf(0.114f, b1.x, fmaf(0.587f, g1.x, 0.299f * r1.x));
        g[j][5] = fmaf(0.114f, b1.y, fmaf(0.587f, g1.y, 0.299f * r1.y));
        g[j][6] = fmaf(0.114f, b1.z, fmaf(0.587f, g1.z, 0.299f * r1.z));
        g[j][7] = fmaf(0.114f, b1.w, fmaf(0.587f, g1.w, 0.299f * r1.w));
    }

    // ---- separable DCT + mask; rows staged into smem ----
    float* sbase = stage + rsel * 4096 + bx * 8;   // my block within the 32KB tile
#pragma unroll
    for (int i = 0; i < 8; ++i) {
        float tr[8];
#pragma unroll
        for (int k = 0; k < 8; ++k) {
            float s = Ds[i * 8 + 0] * g[0][k];
#pragma unroll
            for (int j = 1; j < 8; ++j)
                s = fmaf(Ds[i * 8 + j], g[j][k], s);
            tr[k] = s;
        }
        float o[8];
#pragma unroll
        for (int l = 0; l < 8; ++l) {
            float s = tr[0] * Ds[l * 8 + 0];
#pragma unroll
            for (int k = 1; k < 8; ++k)
                s = fmaf(tr[k], Ds[l * 8 + k], s);
            o[l] = s * Ms[i * 8 + l];
        }
        float* sp = sbase + i * 512;
        *(float4*)(sp)     = make_float4(o[0], o[1], o[2], o[3]);
        *(float4*)(sp + 4) = make_float4(o[4], o[5], o[6], o[7]);
    }

    __syncthreads();

    // ---- one 32KB bulk store: smem tile -> 16 contiguous global image rows ----
    if (t == 0) {
        asm volatile("fence.proxy.async.shared::cta;" ::: "memory");
        float* dst = out + (size_t)b * HW + (size_t)(byp * 16) * W;
        asm volatile(
            "cp.async.bulk.global.shared::cta.bulk_group [%0], [%1], %2;"
            :: "l"(dst), "r"(smem_u32(stage)), "r"(32768) : "memory");
        asm volatile("cp.async.bulk.commit_group;" ::: "memory");
        asm volatile("cp.async.bulk.wait_group 0;" ::: "memory");
    }
}

extern "C" void kernel_launch(void* const* d_in, const int* in_sizes, int n_in,
                              void* d_out, int out_size)
{
    const float* x    = (const float*)d_in[0];
    const float* dctm = (const float*)d_in[1];
    const float* mask = (const float*)d_in[2];
    float* out        = (float*)d_out;

    const int HW = 512 * 512;
    const int B  = in_sizes[0] / (3 * HW);   // 64
    const int ntiles = B * 32;               // 2048 double block-rows

    dct_extract_kernel<<<ntiles, TPB>>>(x, dctm, mask, out, ntiles);
}

// round 16
// speedup vs baseline: 1.3868x; 1.3868x over previous
#include <cuda_runtime.h>
#include <cuda_bf16.h>
#include <cstdint>

// DCTExtractor: gray = 0.299R + 0.587G + 0.114B, per-8x8-block 2D DCT
// (D @ blk @ D^T) * mask, folded back to (B,1,H,W).
//
// Final configuration (best measured across 13 experiments):
//  - one thread per 8x8 block, DCT fully register-resident
//  - 48 front-batched __ldcs LDG.128 reads per thread (evict-first: zero-reuse
//    stream must not pay L2 retention)
//  - TPB=64, one CTA = one 16KB-contiguous output block-row
//  - output staged in smem, written as ONE 16KB cp.async.bulk burst per CTA
//    (large sequential write bursts; STG issue pressure -> 0)
//  - small CTAs retire fast -> CTA replacement keeps fresh load batches
//    in flight (measured: wider CTAs collapse DRAM util 73% -> 49%)
// Kernel 36.8us @ 5.77 TB/s — at the measured mixed-stream HBM ceiling.

#define TPB 64

__device__ __forceinline__ uint32_t smem_u32(const void* p) {
    uint32_t a;
    asm("{ .reg .u64 t; cvta.to.shared.u64 t, %1; cvt.u32.u64 %0, t; }"
        : "=r"(a) : "l"(p));
    return a;
}

__global__ __launch_bounds__(TPB, 8)
void dct_extract_kernel(const float* __restrict__ x,
                        const float* __restrict__ dctm,
                        const float* __restrict__ mask,
                        float* __restrict__ out,
                        int ntiles)
{
    __shared__ float Ds[64];
    __shared__ float Ms[64];
    __shared__ __align__(16) float stage[4096];   // 16KB output tile

    const int t = threadIdx.x;
    Ds[t] = dctm[t];
    Ms[t] = mask[t];
    __syncthreads();

    const int W  = 512;
    const int HW = 512 * 512;

    const int T = blockIdx.x;          // tile = one block-row of one image
    if (T >= ntiles) return;
    const int b  = T >> 6;
    const int by = T & 63;
    const int bx = t;                  // thread owns block column bx

    const float* p0 = x + (size_t)b * 3 * HW + (size_t)(by * 8) * W + bx * 8;

    // ---- load 8x8 grayscale block into registers (LDG.128, evict-first) ----
    float g[8][8];
#pragma unroll
    for (int j = 0; j < 8; ++j) {
        const float* row = p0 + j * W;
        const float4 r0 = __ldcs((const float4*)(row));
        const float4 r1 = __ldcs((const float4*)(row + 4));
        const float4 g0 = __ldcs((const float4*)(row + HW));
        const float4 g1 = __ldcs((const float4*)(row + HW + 4));
        const float4 b0 = __ldcs((const float4*)(row + 2 * HW));
        const float4 b1 = __ldcs((const float4*)(row + 2 * HW + 4));
        g[j][0] = fmaf(0.114f, b0.x, fmaf(0.587f, g0.x, 0.299f * r0.x));
        g[j][1] = fmaf(0.114f, b0.y, fmaf(0.587f, g0.y, 0.299f * r0.y));
        g[j][2] = fmaf(0.114f, b0.z, fmaf(0.587f, g0.z, 0.299f * r0.z));
        g[j][3] = fmaf(0.114f, b0.w, fmaf(0.587f, g0.w, 0.299f * r0.w));
        g[j][4] = fmaf(0.114f, b1.x, fmaf(0.587f, g1.x, 0.299f * r1.x));
        g[j][5] = fmaf(0.114f, b1.y, fmaf(0.587f, g1.y, 0.299f * r1.y));
        g[j][6] = fmaf(0.114f, b1.z, fmaf(0.587f, g1.z, 0.299f * r1.z));
        g[j][7] = fmaf(0.114f, b1.w, fmaf(0.587f, g1.w, 0.299f * r1.w));
    }

    // ---- separable DCT + mask; rows staged into smem ----
#pragma unroll
    for (int i = 0; i < 8; ++i) {
        float tr[8];
#pragma unroll
        for (int k = 0; k < 8; ++k) {
            float s = Ds[i * 8 + 0] * g[0][k];
#pragma unroll
            for (int j = 1; j < 8; ++j)
                s = fmaf(Ds[i * 8 + j], g[j][k], s);
            tr[k] = s;
        }
        float o[8];
#pragma unroll
        for (int l = 0; l < 8; ++l) {
            float s = tr[0] * Ds[l * 8 + 0];
#pragma unroll
            for (int k = 1; k < 8; ++k)
                s = fmaf(tr[k], Ds[l * 8 + k], s);
            o[l] = s * Ms[i * 8 + l];
        }
        float* sp = stage + i * 512 + bx * 8;
        *(float4*)(sp)     = make_float4(o[0], o[1], o[2], o[3]);
        *(float4*)(sp + 4) = make_float4(o[4], o[5], o[6], o[7]);
    }

    __syncthreads();

    // ---- one 16KB bulk store: smem tile -> contiguous global block-row ----
    if (t == 0) {
        asm volatile("fence.proxy.async.shared::cta;" ::: "memory");
        float* dst = out + (size_t)b * HW + (size_t)(by * 8) * W;
        asm volatile(
            "cp.async.bulk.global.shared::cta.bulk_group [%0], [%1], %2;"
            :: "l"(dst), "r"(smem_u32(stage)), "r"(16384) : "memory");
        asm volatile("cp.async.bulk.commit_group;" ::: "memory");
        asm volatile("cp.async.bulk.wait_group 0;" ::: "memory");
    }
}

extern "C" void kernel_launch(void* const* d_in, const int* in_sizes, int n_in,
                              void* d_out, int out_size)
{
    const float* x    = (const float*)d_in[0];
    const float* dctm = (const float*)d_in[1];
    const float* mask = (const float*)d_in[2];
    float* out        = (float*)d_out;

    const int HW = 512 * 512;
    const int B  = in_sizes[0] / (3 * HW);   // 64
    const int ntiles = B * 64;               // 4096 block-rows

    dct_extract_kernel<<<ntiles, TPB>>>(x, dctm, mask, out, ntiles);
}